// round 11
// baseline (speedup 1.0000x reference)
#include <cuda_runtime.h>

#define BATCH 4
#define SEQ   4096
#define EMBED 768
#define HEAD  64
#define NQB   (SEQ / 64)

typedef unsigned long long u64;

// Scratch for projected Q, K, V  (3 x 4 MB). __device__ globals: no allocation.
__device__ float g_Q[BATCH * SEQ * HEAD];
__device__ float g_K[BATCH * SEQ * HEAD];
__device__ float g_V[BATCH * SEQ * HEAD];

// XOR-granule swizzle for [a][b] tiles with 64-float rows (natural layouts).
__device__ __forceinline__ int swz4(int a, int b4) {
    return a * 64 + ((((b4 >> 2) ^ (a >> 2)) & 15) << 2);
}
__device__ __forceinline__ int swz1(int a, int b) {
    return swz4(a, b & ~3) + (b & 3);
}

// ---- packed f32x2 helpers (SASS FFMA2 — only reachable via PTX) ----------
__device__ __forceinline__ void fma2(u64 &d, u64 a, u64 b) {
    asm("fma.rn.f32x2 %0, %1, %2, %0;" : "+l"(d) : "l"(a), "l"(b));
}
__device__ __forceinline__ void mul2(u64 &d, u64 a) {
    asm("mul.rn.f32x2 %0, %0, %1;" : "+l"(d) : "l"(a));
}
__device__ __forceinline__ u64 dup2(float a) {
    u64 r; asm("mov.b64 %0, {%1, %1};" : "=l"(r) : "f"(a)); return r;
}
__device__ __forceinline__ float2 unpk(u64 v) {
    float2 r; asm("mov.b64 {%0, %1}, %2;" : "=f"(r.x), "=f"(r.y) : "l"(v));
    return r;
}
__device__ __forceinline__ float ex2f(float x) {
    float r; asm("ex2.approx.ftz.f32 %0, %1;" : "=f"(r) : "f"(x)); return r;
}

// ---------------------------------------------------------------------------
// QKV projection with FFMA2.
// AsD: x tile transposed + row-pair duplicated: row kk holds 64 m-values as
//      32 granules of (v,v,v',v'); granule t = m-pair, permuted t^(kk>>2).
// Bs : W tile, natural [kk][64].
// ---------------------------------------------------------------------------
__global__ __launch_bounds__(256, 2) void qkv_proj(
    const float* __restrict__ x,
    const float* __restrict__ Wq, const float* __restrict__ bq,
    const float* __restrict__ Wk, const float* __restrict__ bk,
    const float* __restrict__ Wv, const float* __restrict__ bv)
{
    __shared__ float AsD[32 * 128];   // 16 KB dup'd x tile
    __shared__ float Bs [32 * 64];    //  8 KB W tile

    const float* W; const float* bias; float* out;
    if (blockIdx.y == 0)      { W = Wq; bias = bq; out = g_Q; }
    else if (blockIdx.y == 1) { W = Wk; bias = bk; out = g_K; }
    else                      { W = Wv; bias = bv; out = g_V; }

    const int tid = threadIdx.x;
    const int ty = tid >> 4;        // 0..15 -> 4 M rows each
    const int tx = tid & 15;        // 0..15 -> 4 N cols each
    const int mBase = blockIdx.x * 64;

    u64 c2[4][2];
    #pragma unroll
    for (int r = 0; r < 4; r++) { c2[r][0] = 0ull; c2[r][1] = 0ull; }

    for (int k0 = 0; k0 < EMBED; k0 += 32) {
        #pragma unroll
        for (int i = 0; i < 2; i++) {
            int f4 = tid + i * 256;            // 0..511
            int m  = f4 >> 3;                  // 0..63
            int kq = (f4 & 7) << 2;
            float4 v = *(const float4*)&x[(size_t)(mBase + m) * EMBED + k0 + kq];
            float vv[4] = {v.x, v.y, v.z, v.w};
            int g    = m >> 1;
            int slot = (m & 1) << 1;
            #pragma unroll
            for (int c = 0; c < 4; c++) {
                int k = kq + c;
                *(float2*)&AsD[k * 128 + ((((g ^ (k >> 2)) & 31)) << 2) + slot]
                    = make_float2(vv[c], vv[c]);
            }
            int kk = f4 >> 4;
            int h  = (f4 & 15) << 2;
            *(float4*)&Bs[kk * 64 + h] = *(const float4*)&W[(size_t)(k0 + kk) * HEAD + h];
        }
        __syncthreads();

        #pragma unroll
        for (int k4 = 0; k4 < 8; k4++) {
            const float* ap = AsD + (k4 * 4) * 128;
            int pa = (((2 * ty)     ^ k4) & 31) << 2;
            int pb = (((2 * ty + 1) ^ k4) & 31) << 2;
            #pragma unroll
            for (int ki = 0; ki < 4; ki++) {
                ulonglong2 aA = *(const ulonglong2*)(ap + ki * 128 + pa);
                ulonglong2 aB = *(const ulonglong2*)(ap + ki * 128 + pb);
                ulonglong2 b  = *(const ulonglong2*)&Bs[(k4 * 4 + ki) * 64 + (tx << 2)];
                fma2(c2[0][0], aA.x, b.x); fma2(c2[0][1], aA.x, b.y);
                fma2(c2[1][0], aA.y, b.x); fma2(c2[1][1], aA.y, b.y);
                fma2(c2[2][0], aB.x, b.x); fma2(c2[2][1], aB.x, b.y);
                fma2(c2[3][0], aB.y, b.x); fma2(c2[3][1], aB.y, b.y);
            }
        }
        __syncthreads();
    }

    float4 bb = *(const float4*)&bias[tx << 2];
    #pragma unroll
    for (int r = 0; r < 4; r++) {
        float2 a01 = unpk(c2[r][0]);
        float2 a23 = unpk(c2[r][1]);
        float4 o = make_float4(a01.x + bb.x, a01.y + bb.y,
                               a23.x + bb.z, a23.y + bb.w);
        *(float4*)&out[(size_t)(mBase + (ty << 2) + r) * HEAD + (tx << 2)] = o;
    }
}

// ---------------------------------------------------------------------------
// Flash attention, causal. 64x64 tiles, 256 threads, 4x4 micro-tile,
// packed FFMA2 (pairs over key / head columns).
// smem (96 KB dynamic, 2 blocks/SM):
//   QsDup[64 kk][128]  Q rows duplicated, granule perm t^(kk>>2)  (once)
//   Ks   [64 kk][64 j] K transposed, swizzled                      (per iter)
//   Vs   [64 j ][64 h] V, swizzled                                 (per iter)
//   Pdup [64 j ][128]  P rows duplicated, granule perm t^(j>>2)    (per iter)
// K register-prefetched one iter ahead; V LDG at iter top, STS after softmax.
// __launch_bounds__(256,2): regs <= 128 -> 16 warps/SM.
// ---------------------------------------------------------------------------
__global__ __launch_bounds__(256, 2) void attn(float* __restrict__ out)
{
    extern __shared__ float sm[];
    float* QsDup = sm;           // 8192 floats
    float* Ks    = sm + 8192;    // 4096
    float* Vs    = sm + 12288;   // 4096
    float* Pdup  = sm + 16384;   // 8192

    const int b   = blockIdx.y;
    const int qb  = NQB - 1 - blockIdx.x;   // heavy blocks first
    const int tid = threadIdx.x;
    const int ty  = tid >> 4;               // 0..15 query micro-row group
    const int tx  = tid & 15;               // 0..15 key/head micro-col group
    const int lr  = tid >> 4;               // load row base
    const int lh  = (tid & 15) << 2;        // load col

    const float* Qg = g_Q + ((size_t)b * SEQ + (size_t)qb * 64) * HEAD;
    const float* Kg = g_K + (size_t)b * SEQ * HEAD;
    const float* Vg = g_V + (size_t)b * SEQ * HEAD;

    // ---- Q tile -> QsDup (duplicated pairs, permuted granules) ------------
    #pragma unroll
    for (int i = 0; i < 4; i++) {
        int r = lr + i * 16;
        float4 v = *(const float4*)&Qg[(size_t)r * HEAD + lh];
        float vv[4] = {v.x, v.y, v.z, v.w};
        int g    = r >> 1;
        int slot = (r & 1) << 1;
        #pragma unroll
        for (int c = 0; c < 4; c++) {
            int k = lh + c;
            *(float2*)&QsDup[k * 128 + (((g ^ (k >> 2)) & 31) << 2) + slot]
                = make_float2(vv[c], vv[c]);
        }
    }

    u64 acc2[4][2];
    float m_r[4], l_r[4];
    #pragma unroll
    for (int r = 0; r < 4; r++) {
        m_r[r] = -1e30f; l_r[r] = 0.0f;
        acc2[r][0] = 0ull; acc2[r][1] = 0ull;
    }

    // scale folded with log2(e): softmax in exp2 domain
    const float SCALE2 = 0.125f * 1.44269504088896340736f;

    // prefetch K(0) into registers
    float4 kreg[4];
    #pragma unroll
    for (int i = 0; i < 4; i++)
        kreg[i] = *(const float4*)&Kg[(size_t)(lr + 16 * i) * HEAD + lh];

    for (int kb = 0; kb <= qb; kb++) {
        // issue V loads now; stored to smem after softmax
        const float* Vt = Vg + (size_t)kb * 64 * HEAD;
        float4 vreg[4];
        #pragma unroll
        for (int i = 0; i < 4; i++)
            vreg[i] = *(const float4*)&Vt[(size_t)(lr + 16 * i) * HEAD + lh];

        __syncthreads();   // PV(kb-1) finished reading; Ks free

        // store prefetched K transposed (swizzled)
        #pragma unroll
        for (int i = 0; i < 4; i++) {
            int r = lr + 16 * i;
            float kv[4] = {kreg[i].x, kreg[i].y, kreg[i].z, kreg[i].w};
            #pragma unroll
            for (int c = 0; c < 4; c++)
                Ks[swz1(lh + c, r)] = kv[c];
        }
        // prefetch next K tile (completes during QK/softmax)
        if (kb < qb) {
            const float* Kt = Kg + (size_t)(kb + 1) * 64 * HEAD;
            #pragma unroll
            for (int i = 0; i < 4; i++)
                kreg[i] = *(const float4*)&Kt[(size_t)(lr + 16 * i) * HEAD + lh];
        }
        __syncthreads();   // Ks ready (iter 0: QsDup ready too)

        // ---- S = Q K^T : FFMA2 over key-column pairs ----------------------
        u64 s2[4][2];
        s2[0][0]=0ull; s2[0][1]=0ull; s2[1][0]=0ull; s2[1][1]=0ull;
        s2[2][0]=0ull; s2[2][1]=0ull; s2[3][0]=0ull; s2[3][1]=0ull;

        #pragma unroll
        for (int k4 = 0; k4 < 16; k4++) {
            const float* qp = QsDup + (k4 * 4) * 128;
            int pa = (((2 * ty)     ^ k4) & 31) << 2;
            int pb = (((2 * ty + 1) ^ k4) & 31) << 2;
            #pragma unroll
            for (int ki = 0; ki < 4; ki++) {
                ulonglong2 qA = *(const ulonglong2*)(qp + ki * 128 + pa);
                ulonglong2 qB = *(const ulonglong2*)(qp + ki * 128 + pb);
                ulonglong2 kx = *(const ulonglong2*)&Ks[swz4(k4 * 4 + ki, tx << 2)];
                fma2(s2[0][0], qA.x, kx.x); fma2(s2[0][1], qA.x, kx.y);
                fma2(s2[1][0], qA.y, kx.x); fma2(s2[1][1], qA.y, kx.y);
                fma2(s2[2][0], qB.x, kx.x); fma2(s2[2][1], qB.x, kx.y);
                fma2(s2[3][0], qB.y, kx.x); fma2(s2[3][1], qB.y, kx.y);
            }
        }

        // ---- online softmax (scalar, exp2 domain) -------------------------
        float p[4][4];
        #pragma unroll
        for (int r = 0; r < 4; r++) {
            float2 v01 = unpk(s2[r][0]);
            float2 v23 = unpk(s2[r][1]);
            float sr[4] = {v01.x, v01.y, v23.x, v23.y};
            if (kb == qb) {
                int trow = (ty << 2) + r;
                #pragma unroll
                for (int cc = 0; cc < 4; cc++) {
                    int tcol = (tx << 2) + cc;
                    sr[cc] = (tcol <= trow) ? sr[cc] * SCALE2 : -1e30f;
                }
            } else {
                #pragma unroll
                for (int cc = 0; cc < 4; cc++) sr[cc] *= SCALE2;
            }
            float m0 = fmaxf(fmaxf(sr[0], sr[1]), fmaxf(sr[2], sr[3]));
            #pragma unroll
            for (int off = 8; off > 0; off >>= 1)
                m0 = fmaxf(m0, __shfl_xor_sync(0xffffffffu, m0, off));
            float newm  = fmaxf(m_r[r], m0);
            float alpha = ex2f(m_r[r] - newm);
            float lsum  = 0.0f;
            #pragma unroll
            for (int cc = 0; cc < 4; cc++) {
                float e = ex2f(sr[cc] - newm);
                p[r][cc] = e;
                lsum += e;
            }
            #pragma unroll
            for (int off = 8; off > 0; off >>= 1)
                lsum += __shfl_xor_sync(0xffffffffu, lsum, off);
            l_r[r] = l_r[r] * alpha + lsum;
            m_r[r] = newm;
            u64 al = dup2(alpha);
            mul2(acc2[r][0], al);
            mul2(acc2[r][1], al);
        }

        // ---- store P duplicated (permuted granules) + V tile --------------
        #pragma unroll
        for (int cc = 0; cc < 4; cc++) {
            int j = (tx << 2) + cc;
            float* row = Pdup + j * 128;
            int xr = (j >> 2) & 15;          // = tx
            *(float4*)&row[(((2 * ty)     ^ xr) & 31) << 2]
                = make_float4(p[0][cc], p[0][cc], p[1][cc], p[1][cc]);
            *(float4*)&row[(((2 * ty + 1) ^ xr) & 31) << 2]
                = make_float4(p[2][cc], p[2][cc], p[3][cc], p[3][cc]);
        }
        #pragma unroll
        for (int i = 0; i < 4; i++)
            *(float4*)&Vs[swz4(lr + 16 * i, lh)] = vreg[i];

        __syncthreads();   // Pdup + Vs ready

        // ---- O += P V : FFMA2 over head-column pairs ----------------------
        #pragma unroll
        for (int j4 = 0; j4 < 16; j4++) {
            const float* pp = Pdup + (j4 * 4) * 128;
            int pa = (((2 * ty)     ^ j4) & 31) << 2;
            int pb = (((2 * ty + 1) ^ j4) & 31) << 2;
            #pragma unroll
            for (int ji = 0; ji < 4; ji++) {
                ulonglong2 pA = *(const ulonglong2*)(pp + ji * 128 + pa);
                ulonglong2 pB = *(const ulonglong2*)(pp + ji * 128 + pb);
                ulonglong2 vv = *(const ulonglong2*)&Vs[swz4(j4 * 4 + ji, tx << 2)];
                fma2(acc2[0][0], pA.x, vv.x); fma2(acc2[0][1], pA.x, vv.y);
                fma2(acc2[1][0], pA.y, vv.x); fma2(acc2[1][1], pA.y, vv.y);
                fma2(acc2[2][0], pB.x, vv.x); fma2(acc2[2][1], pB.x, vv.y);
                fma2(acc2[3][0], pB.y, vv.x); fma2(acc2[3][1], pB.y, vv.y);
            }
        }
    }

    // ---- epilogue: normalize and store ------------------------------------
    float* Og = out + ((size_t)b * SEQ + (size_t)qb * 64) * HEAD;
    #pragma unroll
    for (int r = 0; r < 4; r++) {
        float inv = 1.0f / l_r[r];
        float2 a01 = unpk(acc2[r][0]);
        float2 a23 = unpk(acc2[r][1]);
        float4 o = make_float4(a01.x * inv, a01.y * inv,
                               a23.x * inv, a23.y * inv);
        *(float4*)&Og[(size_t)((ty << 2) + r) * HEAD + (tx << 2)] = o;
    }
}

// ---------------------------------------------------------------------------
#define ATTN_SMEM (24576 * (int)sizeof(float))   // 96 KB dynamic

extern "C" void kernel_launch(void* const* d_in, const int* in_sizes, int n_in,
                              void* d_out, int out_size)
{
    const float* x  = (const float*)d_in[0];
    const float* Wq = (const float*)d_in[1];
    const float* bq = (const float*)d_in[2];
    const float* Wk = (const float*)d_in[3];
    const float* bk = (const float*)d_in[4];
    const float* Wv = (const float*)d_in[5];
    const float* bv = (const float*)d_in[6];
    float* out = (float*)d_out;

    cudaFuncSetAttribute(attn, cudaFuncAttributeMaxDynamicSharedMemorySize,
                         ATTN_SMEM);

    dim3 gp((BATCH * SEQ) / 64, 3);
    qkv_proj<<<gp, 256>>>(x, Wq, bq, Wk, bk, Wv, bv);

    dim3 ga(NQB, BATCH);
    attn<<<ga, 256, ATTN_SMEM>>>(out);
}

// round 13
// speedup vs baseline: 1.1726x; 1.1726x over previous
#include <cuda_runtime.h>

#define BATCH 4
#define SEQ   4096
#define EMBED 768
#define HEAD  64
#define NQB   (SEQ / 64)

// Scratch for projected Q, K, V  (3 x 4 MB). __device__ globals: no allocation.
__device__ float g_Q[BATCH * SEQ * HEAD];
__device__ float g_K[BATCH * SEQ * HEAD];
__device__ float g_V[BATCH * SEQ * HEAD];

// XOR-granule swizzle for [a][b] tiles with 64-float rows.
__device__ __forceinline__ int swz4(int a, int b4) {
    return a * 64 + ((((b4 >> 2) ^ (a >> 2)) & 15) << 2);
}
__device__ __forceinline__ int swz1(int a, int b) {
    return swz4(a, b & ~3) + (b & 3);
}

__device__ __forceinline__ float ex2f(float x) {
    float r; asm("ex2.approx.ftz.f32 %0, %1;" : "=f"(r) : "f"(x)); return r;
}

// ---------------------------------------------------------------------------
// QKV projection (R6 scalar version — measured 111 us)
// ---------------------------------------------------------------------------
__global__ __launch_bounds__(256) void qkv_proj(
    const float* __restrict__ x,
    const float* __restrict__ Wq, const float* __restrict__ bq,
    const float* __restrict__ Wk, const float* __restrict__ bk,
    const float* __restrict__ Wv, const float* __restrict__ bv)
{
    __shared__ float As[32 * 64];   // x tile, transposed: As[k][m] (swizzled)
    __shared__ float Bs[32 * 64];   // W tile: Bs[k][h]

    const float* W; const float* bias; float* out;
    if (blockIdx.y == 0)      { W = Wq; bias = bq; out = g_Q; }
    else if (blockIdx.y == 1) { W = Wk; bias = bk; out = g_K; }
    else                      { W = Wv; bias = bv; out = g_V; }

    const int tid = threadIdx.x;
    const int ty = tid >> 4;
    const int tx = tid & 15;
    const int mBase = blockIdx.x * 64;

    float c[4][4] = {};

    for (int k0 = 0; k0 < EMBED; k0 += 32) {
        #pragma unroll
        for (int i = 0; i < 2; i++) {
            int f4 = tid + i * 256;
            int m  = f4 >> 3;
            int kq = (f4 & 7) << 2;
            float4 v = *(const float4*)&x[(size_t)(mBase + m) * EMBED + k0 + kq];
            As[swz1(kq + 0, m)] = v.x;
            As[swz1(kq + 1, m)] = v.y;
            As[swz1(kq + 2, m)] = v.z;
            As[swz1(kq + 3, m)] = v.w;
            int kk = f4 >> 4;
            int h  = (f4 & 15) << 2;
            *(float4*)&Bs[kk * 64 + h] = *(const float4*)&W[(size_t)(k0 + kk) * HEAD + h];
        }
        __syncthreads();

        #pragma unroll
        for (int kk = 0; kk < 32; kk++) {
            float4 a4 = *(const float4*)&As[swz4(kk, ty << 2)];
            float4 b4 = *(const float4*)&Bs[kk * 64 + (tx << 2)];
            float a[4] = {a4.x, a4.y, a4.z, a4.w};
            float b[4] = {b4.x, b4.y, b4.z, b4.w};
            #pragma unroll
            for (int r = 0; r < 4; r++)
                #pragma unroll
                for (int cc = 0; cc < 4; cc++)
                    c[r][cc] = fmaf(a[r], b[cc], c[r][cc]);
        }
        __syncthreads();
    }

    float4 bb = *(const float4*)&bias[tx << 2];
    float bv4[4] = {bb.x, bb.y, bb.z, bb.w};
    #pragma unroll
    for (int r = 0; r < 4; r++) {
        float4 o = make_float4(c[r][0] + bv4[0], c[r][1] + bv4[1],
                               c[r][2] + bv4[2], c[r][3] + bv4[3]);
        *(float4*)&out[(size_t)(mBase + (ty << 2) + r) * HEAD + (tx << 2)] = o;
    }
}

// ---------------------------------------------------------------------------
// Flash attention, causal. BLOCK_M = BLOCK_N = 64, H = 64.
// 256 threads (16x16), 4x4 micro-tile. R6 structure, plus:
//   - __launch_bounds__(256, 2): regs <= 128, 48 KB smem -> 2 blocks/SM,
//     16 warps/SM; all 256 blocks resident in ONE wave.
//   - #pragma unroll 8 on the two 64-deep FMA loops (bounds live LDS ranges
//     so the 128-reg cap lands without spills).
//   - exp2-domain softmax (scale pre-multiplied by log2 e).
// smem: Qs (h-major), KPs (K transposed; reused as P^T), Vs. 48 KB static.
// ---------------------------------------------------------------------------
__global__ __launch_bounds__(256, 2) void attn(float* __restrict__ out)
{
    __shared__ float Qs [64 * 64];   // Qs[h][r]  (swizzled)
    __shared__ float KPs[64 * 64];   // Ks[h][j]  -> later P^T[j][r]
    __shared__ float Vs [64 * 64];   // Vs[j][h]  (swizzled)

    const int b   = blockIdx.y;
    const int qb  = NQB - 1 - blockIdx.x;   // heavy blocks first
    const int tid = threadIdx.x;
    const int ty  = tid >> 4;               // query micro-row group
    const int tx  = tid & 15;               // key / head micro-col group

    const float* Qg = g_Q + ((size_t)b * SEQ + (size_t)qb * 64) * HEAD;
    const float* Kg = g_K + (size_t)b * SEQ * HEAD;
    const float* Vg = g_V + (size_t)b * SEQ * HEAD;

    // Load Q tile transposed: Qs[h][r]
    #pragma unroll
    for (int i = 0; i < 4; i++) {
        int f4 = tid + i * 256;          // 0..1023
        int r  = f4 >> 4;                // query row in tile
        int h4 = (f4 & 15) << 2;
        float4 v = *(const float4*)&Qg[(size_t)r * HEAD + h4];
        Qs[swz1(h4 + 0, r)] = v.x;
        Qs[swz1(h4 + 1, r)] = v.y;
        Qs[swz1(h4 + 2, r)] = v.z;
        Qs[swz1(h4 + 3, r)] = v.w;
    }

    float m_r[4], l_r[4], acc[4][4];
    #pragma unroll
    for (int r = 0; r < 4; r++) {
        m_r[r] = -1e30f; l_r[r] = 0.0f;
        #pragma unroll
        for (int cc = 0; cc < 4; cc++) acc[r][cc] = 0.0f;
    }

    // scale folded with log2(e): softmax in exp2 domain
    const float SCALE2 = 0.125f * 1.44269504088896340736f;

    for (int kb = 0; kb <= qb; kb++) {
        const float* Kt = Kg + (size_t)kb * 64 * HEAD;
        const float* Vt = Vg + (size_t)kb * 64 * HEAD;

        __syncthreads();   // prev PV reads (and Q store on iter 0) complete
        #pragma unroll
        for (int i = 0; i < 4; i++) {
            int f4 = tid + i * 256;
            int r  = f4 >> 4;            // key row in tile
            int h4 = (f4 & 15) << 2;
            float4 kv = *(const float4*)&Kt[(size_t)r * HEAD + h4];
            KPs[swz1(h4 + 0, r)] = kv.x;
            KPs[swz1(h4 + 1, r)] = kv.y;
            KPs[swz1(h4 + 2, r)] = kv.z;
            KPs[swz1(h4 + 3, r)] = kv.w;
            float4 vv = *(const float4*)&Vt[(size_t)r * HEAD + h4];
            *(float4*)&Vs[swz4(r, h4)] = vv;
        }
        __syncthreads();

        // S = Q K^T for this tile, in registers
        float s[4][4] = {};
        #pragma unroll 8
        for (int kk = 0; kk < HEAD; kk++) {
            float4 q4 = *(const float4*)&Qs [swz4(kk, ty << 2)];
            float4 k4 = *(const float4*)&KPs[swz4(kk, tx << 2)];
            float qa[4] = {q4.x, q4.y, q4.z, q4.w};
            float ka[4] = {k4.x, k4.y, k4.z, k4.w};
            #pragma unroll
            for (int r = 0; r < 4; r++)
                #pragma unroll
                for (int cc = 0; cc < 4; cc++)
                    s[r][cc] = fmaf(qa[r], ka[cc], s[r][cc]);
        }

        // scale + causal mask (diagonal tile only)
        if (kb == qb) {
            #pragma unroll
            for (int r = 0; r < 4; r++)
                #pragma unroll
                for (int cc = 0; cc < 4; cc++) {
                    int trow = (ty << 2) + r, tcol = (tx << 2) + cc;
                    s[r][cc] = (tcol <= trow) ? s[r][cc] * SCALE2 : -1e30f;
                }
        } else {
            #pragma unroll
            for (int r = 0; r < 4; r++)
                #pragma unroll
                for (int cc = 0; cc < 4; cc++) s[r][cc] *= SCALE2;
        }

        // online softmax per row (rows live in 16-lane groups: same ty)
        #pragma unroll
        for (int r = 0; r < 4; r++) {
            float m0 = fmaxf(fmaxf(s[r][0], s[r][1]), fmaxf(s[r][2], s[r][3]));
            #pragma unroll
            for (int off = 8; off > 0; off >>= 1)
                m0 = fmaxf(m0, __shfl_xor_sync(0xffffffffu, m0, off));
            float newm  = fmaxf(m_r[r], m0);
            float alpha = ex2f(m_r[r] - newm);
            float lsum  = 0.0f;
            #pragma unroll
            for (int cc = 0; cc < 4; cc++) {
                float e = ex2f(s[r][cc] - newm);
                s[r][cc] = e;                 // s becomes P
                lsum += e;
            }
            #pragma unroll
            for (int off = 8; off > 0; off >>= 1)
                lsum += __shfl_xor_sync(0xffffffffu, lsum, off);
            l_r[r] = l_r[r] * alpha + lsum;
            m_r[r] = newm;
            #pragma unroll
            for (int cc = 0; cc < 4; cc++) acc[r][cc] *= alpha;
        }

        __syncthreads();   // all K reads done; KPs now becomes P^T
        #pragma unroll
        for (int cc = 0; cc < 4; cc++) {
            int j = (tx << 2) + cc;
            float4 v = make_float4(s[0][cc], s[1][cc], s[2][cc], s[3][cc]);
            *(float4*)&KPs[swz4(j, ty << 2)] = v;   // P^T[j][r0..r0+3]
        }
        __syncthreads();

        // O += P V
        #pragma unroll 8
        for (int j = 0; j < 64; j++) {
            float4 p4 = *(const float4*)&KPs[swz4(j, ty << 2)];
            float4 v4 = *(const float4*)&Vs [swz4(j, tx << 2)];
            float pa[4] = {p4.x, p4.y, p4.z, p4.w};
            float va[4] = {v4.x, v4.y, v4.z, v4.w};
            #pragma unroll
            for (int r = 0; r < 4; r++)
                #pragma unroll
                for (int cc = 0; cc < 4; cc++)
                    acc[r][cc] = fmaf(pa[r], va[cc], acc[r][cc]);
        }
    }

    // epilogue: normalize and store
    float* Og = out + ((size_t)b * SEQ + (size_t)qb * 64) * HEAD;
    #pragma unroll
    for (int r = 0; r < 4; r++) {
        float inv = 1.0f / l_r[r];
        float4 o = make_float4(acc[r][0] * inv, acc[r][1] * inv,
                               acc[r][2] * inv, acc[r][3] * inv);
        *(float4*)&Og[(size_t)((ty << 2) + r) * HEAD + (tx << 2)] = o;
    }
}

// ---------------------------------------------------------------------------
extern "C" void kernel_launch(void* const* d_in, const int* in_sizes, int n_in,
                              void* d_out, int out_size)
{
    const float* x  = (const float*)d_in[0];
    const float* Wq = (const float*)d_in[1];
    const float* bq = (const float*)d_in[2];
    const float* Wk = (const float*)d_in[3];
    const float* bk = (const float*)d_in[4];
    const float* Wv = (const float*)d_in[5];
    const float* bv = (const float*)d_in[6];
    float* out = (float*)d_out;

    // make sure the 48 KB-static-smem attn kernel can co-reside 2x per SM
    cudaFuncSetAttribute(attn, cudaFuncAttributePreferredSharedMemoryCarveout,
                         (int)cudaSharedmemCarveoutMaxShared);

    dim3 gp((BATCH * SEQ) / 64, 3);
    qkv_proj<<<gp, 256>>>(x, Wq, bq, Wk, bk, Wv, bv);

    dim3 ga(NQB, BATCH);
    attn<<<ga, 256>>>(out);
}

// round 14
// speedup vs baseline: 1.3202x; 1.1259x over previous
#include <cuda_runtime.h>

#define BATCH 4
#define SEQ   4096
#define EMBED 768
#define HEAD  64
#define NQB   (SEQ / 64)

// Scratch for projected Q, K, V  (3 x 4 MB). __device__ globals: no allocation.
__device__ float g_Q[BATCH * SEQ * HEAD];
__device__ float g_K[BATCH * SEQ * HEAD];
__device__ float g_V[BATCH * SEQ * HEAD];

// XOR-granule swizzle for [a][b] tiles with 64-float rows.
__device__ __forceinline__ int swz4(int a, int b4) {
    return a * 64 + ((((b4 >> 2) ^ (a >> 2)) & 15) << 2);
}
__device__ __forceinline__ int swz1(int a, int b) {
    return swz4(a, b & ~3) + (b & 3);
}

__device__ __forceinline__ float ex2f(float x) {
    float r; asm("ex2.approx.ftz.f32 %0, %1;" : "=f"(r) : "f"(x)); return r;
}

// ---------------------------------------------------------------------------
// QKV projection (R6 scalar version — measured ~111 us)
// ---------------------------------------------------------------------------
__global__ __launch_bounds__(256) void qkv_proj(
    const float* __restrict__ x,
    const float* __restrict__ Wq, const float* __restrict__ bq,
    const float* __restrict__ Wk, const float* __restrict__ bk,
    const float* __restrict__ Wv, const float* __restrict__ bv)
{
    __shared__ float As[32 * 64];   // x tile, transposed: As[k][m] (swizzled)
    __shared__ float Bs[32 * 64];   // W tile: Bs[k][h]

    const float* W; const float* bias; float* out;
    if (blockIdx.y == 0)      { W = Wq; bias = bq; out = g_Q; }
    else if (blockIdx.y == 1) { W = Wk; bias = bk; out = g_K; }
    else                      { W = Wv; bias = bv; out = g_V; }

    const int tid = threadIdx.x;
    const int ty = tid >> 4;
    const int tx = tid & 15;
    const int mBase = blockIdx.x * 64;

    float c[4][4] = {};

    for (int k0 = 0; k0 < EMBED; k0 += 32) {
        #pragma unroll
        for (int i = 0; i < 2; i++) {
            int f4 = tid + i * 256;
            int m  = f4 >> 3;
            int kq = (f4 & 7) << 2;
            float4 v = *(const float4*)&x[(size_t)(mBase + m) * EMBED + k0 + kq];
            As[swz1(kq + 0, m)] = v.x;
            As[swz1(kq + 1, m)] = v.y;
            As[swz1(kq + 2, m)] = v.z;
            As[swz1(kq + 3, m)] = v.w;
            int kk = f4 >> 4;
            int h  = (f4 & 15) << 2;
            *(float4*)&Bs[kk * 64 + h] = *(const float4*)&W[(size_t)(k0 + kk) * HEAD + h];
        }
        __syncthreads();

        #pragma unroll
        for (int kk = 0; kk < 32; kk++) {
            float4 a4 = *(const float4*)&As[swz4(kk, ty << 2)];
            float4 b4 = *(const float4*)&Bs[kk * 64 + (tx << 2)];
            float a[4] = {a4.x, a4.y, a4.z, a4.w};
            float b[4] = {b4.x, b4.y, b4.z, b4.w};
            #pragma unroll
            for (int r = 0; r < 4; r++)
                #pragma unroll
                for (int cc = 0; cc < 4; cc++)
                    c[r][cc] = fmaf(a[r], b[cc], c[r][cc]);
        }
        __syncthreads();
    }

    float4 bb = *(const float4*)&bias[tx << 2];
    float bv4[4] = {bb.x, bb.y, bb.z, bb.w};
    #pragma unroll
    for (int r = 0; r < 4; r++) {
        float4 o = make_float4(c[r][0] + bv4[0], c[r][1] + bv4[1],
                               c[r][2] + bv4[2], c[r][3] + bv4[3]);
        *(float4*)&out[(size_t)(mBase + (ty << 2) + r) * HEAD + (tx << 2)] = o;
    }
}

// ---------------------------------------------------------------------------
// Flash attention, causal. BLOCK_M = BLOCK_N = 64, H = 64.
// 256 threads (16x16), 4x4 micro-tile.
//   - FULL unroll on both 64-deep FMA loops -> all LDS addresses are
//     immediates (kills the 22% alu-pipe address overhead seen with unroll 8)
//   - __launch_bounds__(256, 2): 48 KB smem x2 -> 2 blocks/SM, 16 warps,
//     all 256 blocks in one wave
//   - K/V LDGs hoisted above the barrier: L2 latency overlaps barrier wait
//   - exp2-domain softmax (scale pre-multiplied by log2 e)
// smem: Qs (h-major), KPs (K transposed; reused as P^T), Vs. 48 KB static.
// ---------------------------------------------------------------------------
__global__ __launch_bounds__(256, 2) void attn(float* __restrict__ out)
{
    __shared__ float Qs [64 * 64];   // Qs[h][r]  (swizzled)
    __shared__ float KPs[64 * 64];   // Ks[h][j]  -> later P^T[j][r]
    __shared__ float Vs [64 * 64];   // Vs[j][h]  (swizzled)

    const int b   = blockIdx.y;
    const int qb  = NQB - 1 - blockIdx.x;   // heavy blocks first
    const int tid = threadIdx.x;
    const int ty  = tid >> 4;               // query micro-row group
    const int tx  = tid & 15;               // key / head micro-col group
    const int lr  = tid >> 4;               // load row base
    const int lh  = (tid & 15) << 2;        // load col base

    const float* Qg = g_Q + ((size_t)b * SEQ + (size_t)qb * 64) * HEAD;
    const float* Kg = g_K + (size_t)b * SEQ * HEAD;
    const float* Vg = g_V + (size_t)b * SEQ * HEAD;

    // Load Q tile transposed: Qs[h][r]
    #pragma unroll
    for (int i = 0; i < 4; i++) {
        int f4 = tid + i * 256;          // 0..1023
        int r  = f4 >> 4;                // query row in tile
        int h4 = (f4 & 15) << 2;
        float4 v = *(const float4*)&Qg[(size_t)r * HEAD + h4];
        Qs[swz1(h4 + 0, r)] = v.x;
        Qs[swz1(h4 + 1, r)] = v.y;
        Qs[swz1(h4 + 2, r)] = v.z;
        Qs[swz1(h4 + 3, r)] = v.w;
    }

    float m_r[4], l_r[4], acc[4][4];
    #pragma unroll
    for (int r = 0; r < 4; r++) {
        m_r[r] = -1e30f; l_r[r] = 0.0f;
        #pragma unroll
        for (int cc = 0; cc < 4; cc++) acc[r][cc] = 0.0f;
    }

    // scale folded with log2(e): softmax in exp2 domain
    const float SCALE2 = 0.125f * 1.44269504088896340736f;

    for (int kb = 0; kb <= qb; kb++) {
        const float* Kt = Kg + (size_t)kb * 64 * HEAD;
        const float* Vt = Vg + (size_t)kb * 64 * HEAD;

        // hoisted LDGs: issue before the barrier so L2 latency overlaps
        // the wait for slower warps still in the previous PV loop
        float4 kreg[4], vreg[4];
        #pragma unroll
        for (int i = 0; i < 4; i++) {
            kreg[i] = *(const float4*)&Kt[(size_t)(lr + 16 * i) * HEAD + lh];
            vreg[i] = *(const float4*)&Vt[(size_t)(lr + 16 * i) * HEAD + lh];
        }

        __syncthreads();   // prev PV reads (and Q store on iter 0) complete

        #pragma unroll
        for (int i = 0; i < 4; i++) {
            int r = lr + 16 * i;
            float kv[4] = {kreg[i].x, kreg[i].y, kreg[i].z, kreg[i].w};
            #pragma unroll
            for (int c = 0; c < 4; c++)
                KPs[swz1(lh + c, r)] = kv[c];     // K transposed
            *(float4*)&Vs[swz4(r, lh)] = vreg[i];
        }
        __syncthreads();

        // S = Q K^T for this tile, in registers (full unroll: immediates)
        float s[4][4] = {};
        #pragma unroll
        for (int kk = 0; kk < HEAD; kk++) {
            float4 q4 = *(const float4*)&Qs [swz4(kk, ty << 2)];
            float4 k4 = *(const float4*)&KPs[swz4(kk, tx << 2)];
            float qa[4] = {q4.x, q4.y, q4.z, q4.w};
            float ka[4] = {k4.x, k4.y, k4.z, k4.w};
            #pragma unroll
            for (int r = 0; r < 4; r++)
                #pragma unroll
                for (int cc = 0; cc < 4; cc++)
                    s[r][cc] = fmaf(qa[r], ka[cc], s[r][cc]);
        }

        // scale + causal mask (diagonal tile only)
        if (kb == qb) {
            #pragma unroll
            for (int r = 0; r < 4; r++)
                #pragma unroll
                for (int cc = 0; cc < 4; cc++) {
                    int trow = (ty << 2) + r, tcol = (tx << 2) + cc;
                    s[r][cc] = (tcol <= trow) ? s[r][cc] * SCALE2 : -1e30f;
                }
        } else {
            #pragma unroll
            for (int r = 0; r < 4; r++)
                #pragma unroll
                for (int cc = 0; cc < 4; cc++) s[r][cc] *= SCALE2;
        }

        // online softmax per row (rows live in 16-lane groups: same ty)
        #pragma unroll
        for (int r = 0; r < 4; r++) {
            float m0 = fmaxf(fmaxf(s[r][0], s[r][1]), fmaxf(s[r][2], s[r][3]));
            #pragma unroll
            for (int off = 8; off > 0; off >>= 1)
                m0 = fmaxf(m0, __shfl_xor_sync(0xffffffffu, m0, off));
            float newm  = fmaxf(m_r[r], m0);
            float alpha = ex2f(m_r[r] - newm);
            float lsum  = 0.0f;
            #pragma unroll
            for (int cc = 0; cc < 4; cc++) {
                float e = ex2f(s[r][cc] - newm);
                s[r][cc] = e;                 // s becomes P
                lsum += e;
            }
            #pragma unroll
            for (int off = 8; off > 0; off >>= 1)
                lsum += __shfl_xor_sync(0xffffffffu, lsum, off);
            l_r[r] = l_r[r] * alpha + lsum;
            m_r[r] = newm;
            #pragma unroll
            for (int cc = 0; cc < 4; cc++) acc[r][cc] *= alpha;
        }

        __syncthreads();   // all K reads done; KPs now becomes P^T
        #pragma unroll
        for (int cc = 0; cc < 4; cc++) {
            int j = (tx << 2) + cc;
            float4 v = make_float4(s[0][cc], s[1][cc], s[2][cc], s[3][cc]);
            *(float4*)&KPs[swz4(j, ty << 2)] = v;   // P^T[j][r0..r0+3]
        }
        __syncthreads();

        // O += P V (full unroll: immediates)
        #pragma unroll
        for (int j = 0; j < 64; j++) {
            float4 p4 = *(const float4*)&KPs[swz4(j, ty << 2)];
            float4 v4 = *(const float4*)&Vs [swz4(j, tx << 2)];
            float pa[4] = {p4.x, p4.y, p4.z, p4.w};
            float va[4] = {v4.x, v4.y, v4.z, v4.w};
            #pragma unroll
            for (int r = 0; r < 4; r++)
                #pragma unroll
                for (int cc = 0; cc < 4; cc++)
                    acc[r][cc] = fmaf(pa[r], va[cc], acc[r][cc]);
        }
    }

    // epilogue: normalize and store
    float* Og = out + ((size_t)b * SEQ + (size_t)qb * 64) * HEAD;
    #pragma unroll
    for (int r = 0; r < 4; r++) {
        float inv = 1.0f / l_r[r];
        float4 o = make_float4(acc[r][0] * inv, acc[r][1] * inv,
                               acc[r][2] * inv, acc[r][3] * inv);
        *(float4*)&Og[(size_t)((ty << 2) + r) * HEAD + (tx << 2)] = o;
    }
}

// ---------------------------------------------------------------------------
extern "C" void kernel_launch(void* const* d_in, const int* in_sizes, int n_in,
                              void* d_out, int out_size)
{
    const float* x  = (const float*)d_in[0];
    const float* Wq = (const float*)d_in[1];
    const float* bq = (const float*)d_in[2];
    const float* Wk = (const float*)d_in[3];
    const float* bk = (const float*)d_in[4];
    const float* Wv = (const float*)d_in[5];
    const float* bv = (const float*)d_in[6];
    float* out = (float*)d_out;

    // make sure the 48 KB-static-smem attn kernel can co-reside 2x per SM
    cudaFuncSetAttribute(attn, cudaFuncAttributePreferredSharedMemoryCarveout,
                         (int)cudaSharedmemCarveoutMaxShared);

    dim3 gp((BATCH * SEQ) / 64, 3);
    qkv_proj<<<gp, 256>>>(x, Wq, bq, Wk, bk, Wv, bv);

    dim3 ga(NQB, BATCH);
    attn<<<ga, 256>>>(out);
}